// round 9
// baseline (speedup 1.0000x reference)
#include <cuda_runtime.h>
#include <cuda_bf16.h>
#include <cstdint>

#define NN 512
#define MM 512
#define DD 16
#define BIGF 1e10f

// One CTA per batch. Thread t owns DP row i = t+1.
// Anti-diagonal wavefront: R[i][j] = D[i-1][j-1] + softmin(R[i-1][j-1], R[i-1][j], R[i][j-1])
// Distance dot product packed as f32x2 (FFMA2): 8 LDS.64 + 8 packed FMA per cell.
__global__ __launch_bounds__(512, 1)
void softdtw_kernel(const float* __restrict__ x,
                    const float* __restrict__ y,
                    float* __restrict__ out) {
    __shared__ float2 ypk[DD/2][MM];    // ypk[d2][j] = {y[j][2*d2], y[j][2*d2+1]} (8B elems: conflict-free LDS.64)
    __shared__ float  y2s[MM];          // ||y_j||^2
    __shared__ float  dbuf[3][NN + 1];  // rotating anti-diagonals, indexed by row i

    const int b = blockIdx.x;
    const int t = threadIdx.x;          // 0..511

    // ---- load y row t into paired shared + y^2 ----
    const float4* yb4 = reinterpret_cast<const float4*>(y + (size_t)b * MM * DD + (size_t)t * DD);
    float ysum = 0.f;
    #pragma unroll
    for (int q = 0; q < 4; q++) {
        float4 v = yb4[q];
        ypk[2*q+0][t] = make_float2(v.x, v.y);
        ypk[2*q+1][t] = make_float2(v.z, v.w);
        ysum += v.x*v.x + v.y*v.y + v.z*v.z + v.w*v.w;
    }
    y2s[t] = ysum;

    // ---- load x row t into packed 64-bit registers + x^2 ----
    uint64_t xp[DD/2];
    const float4* xb4 = reinterpret_cast<const float4*>(x + (size_t)b * NN * DD + (size_t)t * DD);
    float x2 = 0.f;
    #pragma unroll
    for (int q = 0; q < 4; q++) {
        float4 v = xb4[q];
        asm("mov.b64 %0, {%1,%2};" : "=l"(xp[2*q+0]) : "f"(v.x), "f"(v.y));
        asm("mov.b64 %0, {%1,%2};" : "=l"(xp[2*q+1]) : "f"(v.z), "f"(v.w));
        x2 += v.x*v.x + v.y*v.y + v.z*v.z + v.w*v.w;
    }

    // ---- init diagonal buffers ----
    dbuf[0][t+1] = BIGF; dbuf[1][t+1] = BIGF; dbuf[2][t+1] = BIGF;
    if (t == 0) { dbuf[0][0] = 0.0f; dbuf[1][0] = BIGF; dbuf[2][0] = BIGF; }
    __syncthreads();

    float* d0 = dbuf[0];   // diag k-2
    float* d1 = dbuf[1];   // diag k-1
    float* d2 = dbuf[2];   // diag k (being written)
    const int i = t + 1;   // DP row, 1..512
    float myPrev = BIGF;   // R[i][j-1] == value this thread wrote last step (R[i][0] = BIG)

    for (int k = 2; k <= NN + MM; ++k) {
        const int j = k - i;
        float val = BIGF;
        if ((unsigned)(j - 1) < (unsigned)MM) {
            const float a  = d0[i-1];   // R[i-1][j-1]
            const float bb = d1[i-1];   // R[i-1][j]
            const float c  = myPrev;    // R[i][j-1]
            const int col = j - 1;
            // squared distance D[i-1][j-1]: packed f32x2 dot product
            uint64_t acc = 0ull;        // {0.0f, 0.0f}
            #pragma unroll
            for (int d2i = 0; d2i < DD/2; d2i++) {
                uint64_t yv = *reinterpret_cast<const uint64_t*>(&ypk[d2i][col]);
                asm("fma.rn.f32x2 %0, %1, %2, %3;" : "=l"(acc) : "l"(xp[d2i]), "l"(yv), "l"(acc));
            }
            float lo, hi;
            asm("mov.b64 {%0,%1}, %2;" : "=f"(lo), "=f"(hi) : "l"(acc));
            const float dot  = lo + hi;
            const float dist = fmaf(-2.0f, dot, x2 + y2s[col]);
            // softmin, gamma = 1
            const float m = fminf(a, fminf(bb, c));
            const float s = __expf(m - a) + __expf(m - bb) + __expf(m - c);
            val = dist + m - __logf(s);
        }
        d2[i] = val;
        if (t == 0) d2[0] = BIGF;   // R[0][k] = BIG for k >= 1
        myPrev = val;
        __syncthreads();
        float* tmp = d0; d0 = d1; d1 = d2; d2 = tmp;
    }

    // final cell (N, M) computed by thread i == NN at k == NN+MM
    if (i == NN) out[b] = myPrev;
}

extern "C" void kernel_launch(void* const* d_in, const int* in_sizes, int n_in,
                              void* d_out, int out_size) {
    const float* x = (const float*)d_in[0];
    const float* y = (const float*)d_in[1];
    float* out = (float*)d_out;
    softdtw_kernel<<<64, 512>>>(x, y, out);
}